// round 13
// baseline (speedup 1.0000x reference)
#include <cuda_runtime.h>
#include <cuda_fp16.h>
#include <cstdint>

// ============================================================================
// CellLSTM on GB300 (sm_103a)
//   z = [x|h] @ [Wi|Wf|Wg|Wo] + b ; gates; c' = f*c + i*g ; h' = o*tanh(c')
//   R13: BK=32 slots with SW64 swizzle -> 6-deep ring (was 3x64KB BK=64/SW128).
//   R12 falsified the signaling theory; recurrence P=max(T,(C+T)/S) with
//   measured P~2050 gives C~5100cyc: slot STREAM-IN time dominates. Halving
//   slot size halves stream-in and doubles S -> latency amortized 2x.
// ============================================================================

#if defined(__CUDA_ARCH_FEAT_SM103_ALL) || defined(__CUDA_ARCH_FEAT_SM100_ALL)
#define USE_TCGEN05 1
#else
#define USE_TCGEN05 0
#endif

#define B_DIM 8192
#define T_DIM 1024
#define U_DIM 1024
#define K_DIM 2048
#define N_DIM 4096

#define BM 256              // two M=128 MMA halves
#define BN 256
#define BK 32
#define KTILES (K_DIM / BK)         // 64 k-iterations per tile
#define NTILES_TOTAL ((B_DIM / BM) * (N_DIM / BN))   // 512
#define NTILES_N (N_DIM / BN)       // 16
#define GRID_X 128                  // 512 tiles / 128 = exactly 4 per CTA
#define MAX_TILES_PER_CTA 4
#define GEMM_THREADS 256

// ---------------- scratch (device globals: allocation-rule-safe) -----------
__device__ __align__(16) __half g_A_h[(size_t)B_DIM * K_DIM];
// W transposed & gate-interleaved: row n = u*4 + gate, K-major
__device__ __align__(16) __half g_W_h[(size_t)N_DIM * K_DIM];

// ---------------- arch-neutral helpers -------------------------------------
__device__ __forceinline__ uint32_t smem_u32(const void* p) {
    uint32_t a;
    asm("{ .reg .u64 t; cvta.to.shared.u64 t, %1; cvt.u32.u64 %0, t; }"
        : "=r"(a) : "l"(p));
    return a;
}

// SW64 swizzle: Swizzle<2,4,3> -- bits[5:4] ^= bits[8:7] (64B rows)
#define SWZ64(off) ((off) ^ (((off) >> 3) & 0x30))

__device__ __forceinline__ float tanh_fast(float x) {
    float y;
    asm("tanh.approx.f32 %0, %1;" : "=f"(y) : "f"(x));
    return y;
}

// sigmoid(z) = 0.5*tanh(z/2) + 0.5
__device__ __forceinline__ float fast_sigmoid(float z) {
    return fmaf(0.5f, tanh_fast(0.5f * z), 0.5f);
}

#if USE_TCGEN05
// ---------------- tcgen05 / mbarrier / cp.async helpers --------------------
__device__ __forceinline__ uint32_t elect_one() {
    uint32_t pred;
    asm volatile(
        "{\n\t.reg .pred p;\n\telect.sync _|p, 0xFFFFFFFF;\n\t"
        "selp.b32 %0, 1, 0, p;\n\t}" : "=r"(pred));
    return pred;
}

#define MBARRIER_INIT(addr, cnt) \
    asm volatile("mbarrier.init.shared.b64 [%0], %1;" \
                 :: "r"((uint32_t)(addr)), "r"((uint32_t)(cnt)) : "memory")

#define MBARRIER_INVAL(addr) \
    asm volatile("mbarrier.inval.shared.b64 [%0];" \
                 :: "r"((uint32_t)(addr)) : "memory")

// arrive on mbar when ALL prior cp.asyncs of this thread have completed.
#define CP_ASYNC_MBAR_ARRIVE(addr) \
    asm volatile("cp.async.mbarrier.arrive.noinc.shared::cta.b64 [%0];" \
                 :: "r"((uint32_t)(addr)) : "memory")

#define MBARRIER_WAIT_PARITY(mbar_smem_addr, phase_parity) do { \
    uint32_t _mbar = (uint32_t)(mbar_smem_addr); \
    uint32_t _parity = (uint32_t)(phase_parity); \
    uint32_t _done; \
    asm volatile( \
        "{\n\t.reg .pred p;\n\t" \
        "mbarrier.try_wait.parity.acquire.cta.shared::cta.b64 p, [%1], %2;\n\t" \
        "selp.b32 %0, 1, 0, p;\n\t}" \
        : "=r"(_done) : "r"(_mbar), "r"(_parity) : "memory"); \
    if (!_done) { \
        asm volatile( \
            "{\n\t.reg .pred P1;\n\t" \
            "WAIT_LOOP_%=:\n\t" \
            "mbarrier.try_wait.parity.acquire.cta.shared::cta.b64 P1, [%0], %1, 0x989680;\n\t" \
            "@P1 bra.uni WAIT_DONE_%=;\n\t" \
            "bra.uni WAIT_LOOP_%=;\n\t" \
            "WAIT_DONE_%=:\n\t}" \
            :: "r"(_mbar), "r"(_parity) : "memory"); \
    } \
} while (0)

#define NAMED_BARRIER_SYNC(id, cnt) \
    asm volatile("bar.sync %0, %1;" :: "r"(id), "r"(cnt) : "memory")

#define TCGEN05_ALLOC(smem_result_addr, nCols) \
    asm volatile("tcgen05.alloc.cta_group::1.sync.aligned.shared::cta.b32 [%0], %1;" \
                 :: "r"((uint32_t)(smem_result_addr)), "r"((uint32_t)(nCols)) : "memory")

#define TCGEN05_DEALLOC(tmem_addr, nCols) \
    asm volatile("tcgen05.dealloc.cta_group::1.sync.aligned.b32 %0, %1;" \
                 :: "r"(tmem_addr), "r"((uint32_t)(nCols)))

#define TCGEN05_COMMIT(mbar_smem_addr) \
    asm volatile("tcgen05.commit.cta_group::1.mbarrier::arrive::one.shared::cluster.b64 [%0];" \
                 :: "r"((uint32_t)(mbar_smem_addr)) : "memory")

#define TCGEN05_FENCE_AFTER() \
    asm volatile("tcgen05.fence::after_thread_sync;" ::: "memory")
#define TCGEN05_FENCE_BEFORE() \
    asm volatile("tcgen05.fence::before_thread_sync;" ::: "memory")
#define TCGEN05_WAIT_LD() \
    asm volatile("tcgen05.wait::ld.sync.aligned;" ::: "memory")

#define FENCE_PROXY_ASYNC() \
    asm volatile("fence.proxy.async.shared::cta;" ::: "memory")

__device__ __forceinline__ void cp16(uint32_t dst, const void* src) {
    asm volatile("cp.async.cg.shared.global [%0], [%1], 16;"
                 :: "r"(dst), "l"(src) : "memory");
}

#define TCGEN05_LD_32X32B_X32(r, tmem_addr) \
    asm volatile( \
        "tcgen05.ld.sync.aligned.32x32b.x32.b32 " \
        "{%0, %1, %2, %3, %4, %5, %6, %7, " \
        " %8, %9, %10, %11, %12, %13, %14, %15, " \
        " %16, %17, %18, %19, %20, %21, %22, %23, " \
        " %24, %25, %26, %27, %28, %29, %30, %31}, [%32];" \
        : "=r"((r)[0]),  "=r"((r)[1]),  "=r"((r)[2]),  "=r"((r)[3]), \
          "=r"((r)[4]),  "=r"((r)[5]),  "=r"((r)[6]),  "=r"((r)[7]), \
          "=r"((r)[8]),  "=r"((r)[9]),  "=r"((r)[10]), "=r"((r)[11]), \
          "=r"((r)[12]), "=r"((r)[13]), "=r"((r)[14]), "=r"((r)[15]), \
          "=r"((r)[16]), "=r"((r)[17]), "=r"((r)[18]), "=r"((r)[19]), \
          "=r"((r)[20]), "=r"((r)[21]), "=r"((r)[22]), "=r"((r)[23]), \
          "=r"((r)[24]), "=r"((r)[25]), "=r"((r)[26]), "=r"((r)[27]), \
          "=r"((r)[28]), "=r"((r)[29]), "=r"((r)[30]), "=r"((r)[31]) \
        : "r"(tmem_addr))

// K-major SW64 smem descriptor (ptx_helpers SMEM_DESC_BASE_SW64):
// layout=4 (SW64), version=1, SBO=32 (512B = 8 rows x 64B), LBO=1 (16B)
static constexpr uint64_t SMEM_DESC_BASE_SW64 =
    (uint64_t(4)  << 61) | (uint64_t(1) << 46) |
    (uint64_t(32) << 32) | (uint64_t(1) << 16);

__device__ __forceinline__ uint64_t make_desc64(uint32_t addr) {
    return SMEM_DESC_BASE_SW64 | ((uint64_t)(addr >> 4) & 0x3FFF);
}

// idesc kind::f16, FP16 inputs, f32 accum, M=128 (per MMA stream), N=256
static constexpr uint32_t MMA_IDESC =
    (1u << 4) | (0u << 7) | (0u << 10) | ((BN / 8) << 17) | ((128 / 16) << 24);

__device__ __forceinline__ void mma_f16_ss(uint32_t d, uint64_t ad, uint64_t bd,
                                           uint32_t idesc, uint32_t acc) {
    asm volatile(
        "{\n\t.reg .pred p;\n\t"
        "setp.ne.u32 p, %4, 0;\n\t"
        "tcgen05.mma.cta_group::1.kind::f16 [%0], %1, %2, %3, {%5, %5, %5, %5}, p;\n\t"
        "}"
        :: "r"(d), "l"(ad), "l"(bd), "r"(idesc), "r"(acc), "r"(0u)
        : "memory");
}
#endif // USE_TCGEN05

// ---------------- fused prep kernel -----------------------------------------
#define PREP_A_BLOCKS ((int)(((size_t)B_DIM * K_DIM / 8) / 256))   // 8192
#define PREP_W_BLOCKS ((K_DIM / 32) * (U_DIM / 32) * 4)            // 8192

__global__ void prep_fused_kernel(const float* __restrict__ x,
                                  const float* __restrict__ h,
                                  const float* __restrict__ Wi,
                                  const float* __restrict__ Wf,
                                  const float* __restrict__ Wg,
                                  const float* __restrict__ Wo) {
    __shared__ float tile[32][33];
    int bid = blockIdx.x;
    int tid = threadIdx.x;

    if (bid < PREP_A_BLOCKS) {
        size_t idx8 = ((size_t)bid * 256 + tid) * 8;
        int m = (int)(idx8 / K_DIM);
        int k = (int)(idx8 % K_DIM);
        const float* src = (k < T_DIM) ? (x + (size_t)m * T_DIM + k)
                                       : (h + (size_t)m * U_DIM + (k - T_DIM));
        float4 v0 = *reinterpret_cast<const float4*>(src);
        float4 v1 = *reinterpret_cast<const float4*>(src + 4);

        union Pack { __half b[8]; uint4 u; } p;
        p.b[0] = __float2half_rn(v0.x); p.b[1] = __float2half_rn(v0.y);
        p.b[2] = __float2half_rn(v0.z); p.b[3] = __float2half_rn(v0.w);
        p.b[4] = __float2half_rn(v1.x); p.b[5] = __float2half_rn(v1.y);
        p.b[6] = __float2half_rn(v1.z); p.b[7] = __float2half_rn(v1.w);
        *reinterpret_cast<uint4*>(g_A_h + idx8) = p.u;
    } else {
        int w = bid - PREP_A_BLOCKS;               // 0..8191
        int gate = w >> 11;
        int rem = w & 2047;
        int k0 = (rem & 63) * 32;
        int u0 = (rem >> 6) * 32;
        const float* W = (gate == 0) ? Wi : (gate == 1) ? Wf
                        : (gate == 2) ? Wg : Wo;
        int tx = tid & 31;
        int ty = tid >> 5;

#pragma unroll
        for (int i = 0; i < 4; i++) {
            int k = k0 + ty + i * 8;
            tile[ty + i * 8][tx] = W[(size_t)k * U_DIM + u0 + tx];
        }
        __syncthreads();
#pragma unroll
        for (int i = 0; i < 4; i++) {
            int u = u0 + ty + i * 8;
            float v = tile[tx][ty + i * 8];        // = W[k0+tx, u]
            size_t off = (size_t)(u * 4 + gate) * K_DIM + k0 + tx;
            g_W_h[off] = __float2half_rn(v);
        }
    }
}

// ---------------- GEMM + LSTM epilogue -------------------------------------
// SMEM map:
//   [0]      tmem ptr
//   [8]      full[6] mbarriers   -- cp.async.mbarrier.arrive (data landed)
//   [64]     mma[6]  mbarriers   -- MMA commit frees a slot
//   [1024]   6 stages x (A 16K + B 16K) = 192KB ring, SW64 64B rows
#define SM_TMEM 0
#define SM_FULL 8
#define SM_MMAB 64
#define SM_STAGE 1024
#define A_TILE_BYTES 16384                  // 256 rows x 64B
#define B_TILE_BYTES 16384                  // 256 rows x 64B
#define STAGE_BYTES (A_TILE_BYTES + B_TILE_BYTES)           // 32768
#define NSTAGES 6
#define GEMM_SMEM (SM_STAGE + NSTAGES * STAGE_BYTES)        // 197632
#define N_PRODUCER_THREADS 128

#if USE_TCGEN05
// Each of the 128 producer threads loads 16 x 16B chunks (A then B), SW64.
__device__ __forceinline__ void load_stage_quarter(uint32_t sbase, int kt,
                                                   int m0, int n0, int ptid) {
    int koff = kt * BK;
    // A: 256 rows x 4 chunks of 16B (1024 chunks) -> 8 per producer thread
#pragma unroll
    for (int j = 0; j < 8; j++) {
        int i = ptid + j * N_PRODUCER_THREADS;
        int r = i >> 2;
        int c = i & 3;
        uint32_t soff = SWZ64((uint32_t)(r * 64 + c * 16));
        size_t ga = (size_t)(m0 + r) * K_DIM + koff + c * 8;
        cp16(sbase + soff, g_A_h + ga);
    }
    uint32_t bbase = sbase + A_TILE_BYTES;
#pragma unroll
    for (int j = 0; j < 8; j++) {
        int i = ptid + j * N_PRODUCER_THREADS;
        int r = i >> 2;
        int c = i & 3;
        uint32_t soff = SWZ64((uint32_t)(r * 64 + c * 16));
        size_t gb = (size_t)(n0 + r) * K_DIM + koff + c * 8;
        cp16(bbase + soff, g_W_h + gb);
    }
}
#endif

__global__ void __launch_bounds__(GEMM_THREADS)
lstm_gemm_kernel(const float* __restrict__ c_in,
                 const float* __restrict__ bi, const float* __restrict__ bf_,
                 const float* __restrict__ bg, const float* __restrict__ bo,
                 float* __restrict__ out) {
    extern __shared__ char smem[];
    int tid = threadIdx.x;
    const size_t c_off = (size_t)B_DIM * U_DIM;

    // tiles owned by this CTA (persistent): exactly 4 at GRID_X=128
    int tiles[MAX_TILES_PER_CTA];
    int ntiles = 0;
    for (int t = blockIdx.x; t < NTILES_TOTAL && ntiles < MAX_TILES_PER_CTA;
         t += GRID_X)
        tiles[ntiles++] = t;
    if (ntiles == 0) return;

#if USE_TCGEN05
    // ======================= warp-specialized persistent path ===============
    uint32_t sb = smem_u32(smem);
    int wid = tid >> 5;
    int lid = tid & 31;

    if (wid == 0) TCGEN05_ALLOC(sb + SM_TMEM, 512);
    if (tid == 0) {
#pragma unroll
        for (int s = 0; s < NSTAGES; s++) {
            MBARRIER_INIT(sb + SM_FULL + 8 * s, N_PRODUCER_THREADS);
            MBARRIER_INIT(sb + SM_MMAB + 8 * s, 1);
        }
    }
    __syncthreads();
    uint32_t tmem;
    asm volatile("ld.shared.b32 %0, [%1];" : "=r"(tmem) : "r"(sb + SM_TMEM));

    const int G = ntiles * KTILES;

    if (wid >= 4) {
        // =================== PRODUCER warps 4-7 =============================
        int ptid = tid - 128;    // 0..127

        // prologue: fill all 6 slots (no gating needed for gp < NSTAGES)
#pragma unroll 1
        for (int gp = 0; gp < NSTAGES && gp < G; gp++) {
            int j2 = gp >> 6;                       // KTILES == 64
            int kt2 = gp & 63;
            int t2 = tiles[j2];
            load_stage_quarter(sb + SM_STAGE + gp * STAGE_BYTES, kt2,
                               (t2 >> 4) * BM, (t2 & (NTILES_N - 1)) * BN, ptid);
            CP_ASYNC_MBAR_ARRIVE(sb + SM_FULL + 8 * gp);
        }

#pragma unroll 1
        for (int gp = NSTAGES; gp < G; gp++) {
            // slot gp%6 was consumed by MMA(gp-6): wait its commit
            int w = gp - NSTAGES;
            MBARRIER_WAIT_PARITY(sb + SM_MMAB + 8 * (w % NSTAGES),
                                 (w / NSTAGES) & 1);
            int j2 = gp >> 6;
            int kt2 = gp & 63;
            int t2 = tiles[j2];
            load_stage_quarter(sb + SM_STAGE + (gp % NSTAGES) * STAGE_BYTES,
                               kt2, (t2 >> 4) * BM,
                               (t2 & (NTILES_N - 1)) * BN, ptid);
            CP_ASYNC_MBAR_ARRIVE(sb + SM_FULL + 8 * (gp % NSTAGES));
        }

    } else {
        // =================== CONSUMER warps 0-3 =============================
        int g = 0;
#pragma unroll 1
        for (int j = 0; j < ntiles; j++) {
            int t = tiles[j];
            int m0 = (t >> 4) * BM;
            int n0 = (t & (NTILES_N - 1)) * BN;
            int u_base = n0 >> 2;

            if (wid == 0) {
#pragma unroll 1
                for (int kt = 0; kt < KTILES; kt++, g++) {
                    MBARRIER_WAIT_PARITY(sb + SM_FULL + 8 * (g % NSTAGES),
                                         (g / NSTAGES) & 1);
                    uint32_t st = sb + SM_STAGE + (g % NSTAGES) * STAGE_BYTES;
                    uint64_t dA0 = make_desc64(st);           // rows 0..127
                    uint64_t dA1 = make_desc64(st + 8192);    // rows 128..255
                    uint64_t dB  = make_desc64(st + A_TILE_BYTES);
                    if (elect_one()) {
                        FENCE_PROXY_ASYNC();
#pragma unroll
                        for (int s = 0; s < 2; s++) {         // 2 x K=16 steps
                            uint32_t off = s * 2;             // 32B = 2 units
                            uint32_t acc = (kt | s) != 0;
                            mma_f16_ss(tmem,       dA0 + off, dB + off, MMA_IDESC, acc);
                            mma_f16_ss(tmem + 256, dA1 + off, dB + off, MMA_IDESC, acc);
                        }
                        TCGEN05_COMMIT(sb + SM_MMAB + 8 * (g % NSTAGES));
                    }
                }
                // wait last MMA of this tile before epilogue
                int gl = g - 1;
                MBARRIER_WAIT_PARITY(sb + SM_MMAB + 8 * (gl % NSTAGES),
                                     (gl / NSTAGES) & 1);
            } else {
                g += KTILES;   // warps 1-3 skip the mainloop
            }

            // warps 0-3 rendezvous: warp 0 arrives only after gl commit
            NAMED_BARRIER_SYNC(1, 128);
            TCGEN05_FENCE_AFTER();

            // ------- epilogue: warp w owns D lanes w*32+lid (all 512 cols) --
#pragma unroll
            for (int mh = 0; mh < 2; mh++) {
                int m = m0 + mh * 128 + wid * 32 + lid;
                const float* crow = c_in + (size_t)m * U_DIM;
                float* hrow = out + (size_t)m * U_DIM;
                float* corow = out + c_off + (size_t)m * U_DIM;
#pragma unroll
                for (int ch = 0; ch < 8; ch++) {
                    uint32_t col = (uint32_t)(mh * 256 + ch * 32);
                    uint32_t d[32];
                    TCGEN05_LD_32X32B_X32(d, tmem + col);
                    int u0c = u_base + ch * 8;
                    float4 cv0 = *reinterpret_cast<const float4*>(crow + u0c);
                    float4 cv1 = *reinterpret_cast<const float4*>(crow + u0c + 4);
                    float cvs[8] = {cv0.x, cv0.y, cv0.z, cv0.w,
                                    cv1.x, cv1.y, cv1.z, cv1.w};
                    TCGEN05_WAIT_LD();
                    float hv[8], cnv[8];
#pragma unroll
                    for (int q = 0; q < 8; q++) {
                        int u = u0c + q;
                        float zi = __uint_as_float(d[4 * q + 0]) + bi[u];
                        float zf = __uint_as_float(d[4 * q + 1]) + bf_[u];
                        float zg = __uint_as_float(d[4 * q + 2]) + bg[u];
                        float zo = __uint_as_float(d[4 * q + 3]) + bo[u];
                        float ig = fast_sigmoid(zi);
                        float fg = fast_sigmoid(zf);
                        float gg = tanh_fast(zg);
                        float og = fast_sigmoid(zo);
                        float cn = fg * cvs[q] + ig * gg;
                        hv[q] = og * tanh_fast(cn);
                        cnv[q] = cn;
                    }
                    *reinterpret_cast<float4*>(hrow + u0c) =
                        make_float4(hv[0], hv[1], hv[2], hv[3]);
                    *reinterpret_cast<float4*>(hrow + u0c + 4) =
                        make_float4(hv[4], hv[5], hv[6], hv[7]);
                    *reinterpret_cast<float4*>(corow + u0c) =
                        make_float4(cnv[0], cnv[1], cnv[2], cnv[3]);
                    *reinterpret_cast<float4*>(corow + u0c + 4) =
                        make_float4(cnv[4], cnv[5], cnv[6], cnv[7]);
                }
            }
            TCGEN05_WAIT_LD();
            TCGEN05_FENCE_BEFORE();
            // all warps 0-3 done reading D before next tile's acc=0 MMA
            NAMED_BARRIER_SYNC(1, 128);
        }
    }

    __syncthreads();
    if (tid == 0) {
#pragma unroll
        for (int s = 0; s < NSTAGES; s++) {
            MBARRIER_INVAL(sb + SM_FULL + 8 * s);
            MBARRIER_INVAL(sb + SM_MMAB + 8 * s);
        }
    }
    __syncthreads();
    if (wid == 0) TCGEN05_DEALLOC(tmem, 512);

#else
    // ======================= SIMT fallback (plain sm_103 target) ===========
    const int PAD = 132;
    float* As = reinterpret_cast<float*>(smem);          // [32][PAD]
    float* Bs = As + 32 * PAD;                           // [32][PAD]

    int tx = tid & 15;
    int ty = tid >> 4;

#pragma unroll 1
    for (int j = 0; j < ntiles; j++) {
        int t = tiles[j];
        int m0 = (t >> 4) * BM;
        int n0 = (t & (NTILES_N - 1)) * BN;

#pragma unroll 1
        for (int mh = 0; mh < 2; mh++) {
            int m0h = m0 + mh * 128;
#pragma unroll 1
            for (int ns = 0; ns < 2; ns++) {
                int n0h = n0 + ns * 128;
                int u0 = n0h >> 2;
                float acc[8][8];
#pragma unroll
                for (int i = 0; i < 8; i++)
#pragma unroll
                    for (int q = 0; q < 8; q++) acc[i][q] = 0.0f;

#pragma unroll 1
                for (int kt = 0; kt < K_DIM / 32; kt++) {
                    int koff = kt * 32;
#pragma unroll
                    for (int i = 0; i < 16; i++) {
                        int idx = tid + i * 256;
                        int kk = idx & 31;
                        int r = idx >> 5;
                        size_t ga = (size_t)(m0h + r) * K_DIM + koff + kk;
                        size_t gb = (size_t)(n0h + r) * K_DIM + koff + kk;
                        As[kk * PAD + r] = __half2float(g_A_h[ga]);
                        Bs[kk * PAD + r] = __half2float(g_W_h[gb]);
                    }
                    __syncthreads();
#pragma unroll 1
                    for (int kk = 0; kk < 32; kk++) {
                        float a[8], b[8];
#pragma unroll
                        for (int i = 0; i < 8; i++) a[i] = As[kk * PAD + ty * 8 + i];
#pragma unroll
                        for (int q = 0; q < 8; q++) b[q] = Bs[kk * PAD + tx * 8 + q];
#pragma unroll
                        for (int i = 0; i < 8; i++)
#pragma unroll
                            for (int q = 0; q < 8; q++) acc[i][q] += a[i] * b[q];
                    }
                    __syncthreads();
                }

#pragma unroll
                for (int i = 0; i < 8; i++) {
                    int m = m0h + ty * 8 + i;
#pragma unroll
                    for (int jj = 0; jj < 2; jj++) {
                        int u = u0 + tx * 2 + jj;
                        float zi = acc[i][jj * 4 + 0] + bi[u];
                        float zf = acc[i][jj * 4 + 1] + bf_[u];
                        float zg = acc[i][jj * 4 + 2] + bg[u];
                        float zo = acc[i][jj * 4 + 3] + bo[u];
                        float ig = fast_sigmoid(zi);
                        float fg = fast_sigmoid(zf);
                        float gg = tanh_fast(zg);
                        float og = fast_sigmoid(zo);
                        float cv = c_in[(size_t)m * U_DIM + u];
                        float cn = fg * cv + ig * gg;
                        float hn = og * tanh_fast(cn);
                        out[(size_t)m * U_DIM + u] = hn;
                        out[c_off + (size_t)m * U_DIM + u] = cn;
                    }
                }
                __syncthreads();
            }
        }
    }
#endif
}

// ---------------- launch ----------------------------------------------------
extern "C" void kernel_launch(void* const* d_in, const int* in_sizes, int n_in,
                              void* d_out, int out_size) {
    const float* x  = (const float*)d_in[0];
    const float* h  = (const float*)d_in[1];
    const float* c  = (const float*)d_in[2];
    const float* Wi = (const float*)d_in[3];
    const float* Wf = (const float*)d_in[4];
    const float* Wg = (const float*)d_in[5];
    const float* Wo = (const float*)d_in[6];
    const float* bi = (const float*)d_in[7];
    const float* bf = (const float*)d_in[8];
    const float* bg = (const float*)d_in[9];
    const float* bo = (const float*)d_in[10];
    float* out = (float*)d_out;

    // 1) fused prep: concat->fp16 A  +  W transpose->fp16 (one launch)
    prep_fused_kernel<<<PREP_A_BLOCKS + PREP_W_BLOCKS, 256>>>(
        x, h, Wi, Wf, Wg, Wo);
    // 2) persistent warp-specialized GEMM + LSTM epilogue (6-deep SW64 ring)
    cudaFuncSetAttribute(lstm_gemm_kernel,
                         cudaFuncAttributeMaxDynamicSharedMemorySize, GEMM_SMEM);
    lstm_gemm_kernel<<<GRID_X, GEMM_THREADS, GEMM_SMEM>>>(
        c, bi, bf, bg, bo, out);
}